// round 15
// baseline (speedup 1.0000x reference)
#include <cuda_runtime.h>
#include <cuda_fp16.h>
#include <math.h>

#define NN    50000
#define FIN   256
#define HHID  256
#define NH    4
#define HID   64
#define OUTC  64
#define NE    800000
#define NET   (NE + NN)
#define SLOPE 0.2f

// ---------------- device scratch ----------------
__device__ __half g_xh[NN * FIN];
__device__ __half g_w1t[HHID * FIN];
__device__ __half g_w2t[OUTC * HHID];
__device__ char   g_h1q[NN * HHID];    // x @ W1, int8 col-scaled
__device__ float  g_cscale[HHID];      // dequant scale per column
__device__ float  g_cinv[HHID];        // quant inv-scale per column
__device__ __half g_heluh[NN * HHID];
__device__ __half g_h2h[NN * OUTC];
__device__ float g_as1[NN * NH];
__device__ float g_ad1[NN * NH];
__device__ float g_as2[NN];
__device__ float g_ad2[NN];
__device__ __align__(16) int g_deg[NN];
__device__ __align__(16) int g_cursor[NN];
__device__ __align__(16) int g_row[NN + 4];
__device__ int g_csr[NET];
__device__ int g_bsums[128];

// ---------------- helpers ----------------
__device__ __forceinline__ float warpSum(float v) {
    #pragma unroll
    for (int o = 16; o; o >>= 1) v += __shfl_xor_sync(0xFFFFFFFFu, v, o);
    return v;
}
__device__ __forceinline__ int warpSumI(int v) {
    #pragma unroll
    for (int o = 16; o; o >>= 1) v += __shfl_xor_sync(0xFFFFFFFFu, v, o);
    return v;
}
__device__ __forceinline__ float warpMax(float v) {
    #pragma unroll
    for (int o = 16; o; o >>= 1) v = fmaxf(v, __shfl_xor_sync(0xFFFFFFFFu, v, o));
    return v;
}
__device__ __forceinline__ float lrelu(float a) { return a > 0.f ? a : SLOPE * a; }
__device__ __forceinline__ uint2 ldcg8(const uint2* p) {
    uint2 v;
    asm volatile("ld.global.cg.v2.u32 {%0,%1}, [%2];" : "=r"(v.x), "=r"(v.y) : "l"(p));
    return v;
}
__device__ __forceinline__ unsigned ldcg4(const unsigned* p) {
    unsigned v;
    asm volatile("ld.global.cg.u32 %0, [%1];" : "=r"(v) : "l"(p));
    return v;
}
template<int B>
__device__ __forceinline__ float i8f(unsigned v) {
    return (float)((int)(v << (24 - 8 * B)) >> 24);
}
__device__ __forceinline__ char q8(float v) {
    return (char)__float2int_rn(fminf(fmaxf(v, -127.f), 127.f));
}

// ---------------- fused conversion: x + W1^T + W2^T fp16, W1 column norms ----------------
#define CVT_XBLK (NN * FIN / 1024)   // 12500
__global__ void cvt_k(const float* __restrict__ x, const float* __restrict__ W1,
                      const float* __restrict__ W2) {
    int b = blockIdx.x;
    if (b < CVT_XBLK) {
        int i = (b * 256 + threadIdx.x) * 4;
        float4 v = *(const float4*)&x[i];
        *(__half2*)&g_xh[i]     = __float22half2_rn(make_float2(v.x, v.y));
        *(__half2*)&g_xh[i + 2] = __float22half2_rn(make_float2(v.z, v.w));
    } else if (b < CVT_XBLK + 16) {
        int base = (b - CVT_XBLK) * 4096 + threadIdx.x;
        #pragma unroll
        for (int it = 0; it < 16; it++) {
            int idx = base + it * 256;
            int k = idx >> 8, n = idx & 255;
            g_w1t[n * 256 + k] = __float2half(W1[idx]);
        }
    } else if (b < CVT_XBLK + 20) {
        int base = (b - CVT_XBLK - 16) * 4096 + threadIdx.x;
        #pragma unroll
        for (int it = 0; it < 16; it++) {
            int idx = base + it * 256;
            int k = idx >> 6, n = idx & 63;
            g_w2t[n * 256 + k] = __float2half(W2[idx]);
        }
    } else {
        // per-column norms of W1 -> int8 quant scales (5.5 sigma clamp)
        int j = threadIdx.x;
        float s = 0.f;
        for (int k = 0; k < FIN; k++) {
            float w = W1[k * HHID + j];
            s += w * w;
        }
        float nrm = sqrtf(s);
        g_cscale[j] = 5.5f * nrm / 127.f;
        g_cinv[j]   = 127.f / (5.5f * nrm);
    }
}

// ---------------- fp16 GEMM, cp.async + ldmatrix, fused attention epilogue ----------------
#define TBM 128
#define TBN 64
#define TBK 64
#define AST 72
#define BST 72
#define GEMM_SMEM ((2 * TBM * AST + 2 * TBN * BST) * 2)

__device__ __forceinline__ void cp16(unsigned dst, const void* src, int sz) {
    asm volatile("cp.async.cg.shared.global [%0], [%1], 16, %2;\n"
                 :: "r"(dst), "l"(src), "r"(sz));
}
__device__ __forceinline__ void ldsm4(unsigned& r0, unsigned& r1, unsigned& r2, unsigned& r3,
                                      unsigned addr) {
    asm volatile("ldmatrix.sync.aligned.m8n8.x4.shared.b16 {%0,%1,%2,%3}, [%4];"
                 : "=r"(r0), "=r"(r1), "=r"(r2), "=r"(r3) : "r"(addr));
}
#define MMA_H16(accv, a0, a1, a2, a3, b0, b1)                                    \
    asm volatile("mma.sync.aligned.m16n8k16.row.col.f32.f16.f16.f32 "            \
                 "{%0,%1,%2,%3}, {%4,%5,%6,%7}, {%8,%9}, {%0,%1,%2,%3};"         \
                 : "+f"(accv[0]), "+f"(accv[1]), "+f"(accv[2]), "+f"(accv[3])    \
                 : "r"(a0), "r"(a1), "r"(a2), "r"(a3), "r"(b0), "r"(b1))

template<bool Q8>
__global__ __launch_bounds__(256, 4) void gemm_h16_k(
        const __half* __restrict__ A, const __half* __restrict__ Bt,
        __half* __restrict__ C, char* __restrict__ C8, const float* __restrict__ cinv,
        float* __restrict__ asOut, float* __restrict__ adOut,
        const float* __restrict__ attS, const float* __restrict__ attD,
        int asStr, int M, int Ncol, int K) {
    extern __shared__ char smem[];
    __half* As = (__half*)smem;
    __half* Bs = (__half*)smem + 2 * TBM * AST;
    const unsigned As_u = (unsigned)__cvta_generic_to_shared(As);
    const unsigned Bs_u = (unsigned)__cvta_generic_to_shared(Bs);

    const int tid = threadIdx.x;
    const int bm0 = blockIdx.y * TBM;
    const int bn0 = blockIdx.x * TBN;
    const int warpId = tid >> 5;
    const int lane = tid & 31;
    const int g  = lane >> 2;
    const int tg = lane & 3;
    const int wm = (warpId & 3) * 32;
    const int wn = (warpId >> 2) * 32;

    const int aRow = lane & 15;
    const int aCol = (lane >> 4) * 8;
    const int bRowP = ((lane >> 4) * 8) + (lane & 7);
    const int bCol = ((lane >> 3) & 1) * 8;

    float acc[2][4][4];
    #pragma unroll
    for (int i = 0; i < 2; i++)
        #pragma unroll
        for (int j = 0; j < 4; j++)
            #pragma unroll
            for (int r = 0; r < 4; r++) acc[i][j][r] = 0.f;

    const int KT = K / TBK;

    auto loadTile = [&](int kt, int buf) {
        int k0 = kt * TBK;
        unsigned aBase = As_u + (unsigned)buf * TBM * AST * 2;
        unsigned bBase = Bs_u + (unsigned)buf * TBN * BST * 2;
        #pragma unroll
        for (int it = 0; it < 4; it++) {
            int idx = tid + it * 256;
            int m = idx >> 3, ch = idx & 7;
            const __half* src = A + (size_t)(bm0 + m) * K + k0 + ch * 8;
            int sz = (bm0 + m < M) ? 16 : 0;
            cp16(aBase + (unsigned)(m * AST + ch * 8) * 2, src, sz);
        }
        #pragma unroll
        for (int it = 0; it < 2; it++) {
            int idx = tid + it * 256;
            int n = idx >> 3, ch = idx & 7;
            const __half* src = Bt + (size_t)(bn0 + n) * K + k0 + ch * 8;
            cp16(bBase + (unsigned)(n * BST + ch * 8) * 2, src, 16);
        }
        asm volatile("cp.async.commit_group;\n");
    };

    loadTile(0, 0);

    for (int kt = 0; kt < KT; kt++) {
        if (kt + 1 < KT) {
            loadTile(kt + 1, (kt + 1) & 1);
            asm volatile("cp.async.wait_group 1;\n");
        } else {
            asm volatile("cp.async.wait_group 0;\n");
        }
        __syncthreads();

        unsigned AbU = As_u + (unsigned)(kt & 1) * TBM * AST * 2;
        unsigned BbU = Bs_u + (unsigned)(kt & 1) * TBN * BST * 2;

        #pragma unroll
        for (int kc = 0; kc < TBK; kc += 16) {
            unsigned af[2][4], bf[4][2];
            #pragma unroll
            for (int mt = 0; mt < 2; mt++) {
                unsigned addr = AbU + (unsigned)((wm + mt * 16 + aRow) * AST + kc + aCol) * 2;
                ldsm4(af[mt][0], af[mt][1], af[mt][2], af[mt][3], addr);
            }
            #pragma unroll
            for (int p = 0; p < 2; p++) {
                unsigned addr = BbU + (unsigned)((wn + p * 16 + bRowP) * BST + kc + bCol) * 2;
                ldsm4(bf[2 * p][0], bf[2 * p][1], bf[2 * p + 1][0], bf[2 * p + 1][1], addr);
            }
            #pragma unroll
            for (int mt = 0; mt < 2; mt++)
                #pragma unroll
                for (int nt = 0; nt < 4; nt++)
                    MMA_H16(acc[mt][nt], af[mt][0], af[mt][1], af[mt][2], af[mt][3],
                            bf[nt][0], bf[nt][1]);
        }
        __syncthreads();
    }

    // ---- epilogue: C store (fp16 or int8) ----
    #pragma unroll
    for (int mt = 0; mt < 2; mt++) {
        int r0 = bm0 + wm + mt * 16 + g;
        #pragma unroll
        for (int nt = 0; nt < 4; nt++) {
            int c = bn0 + wn + nt * 8 + tg * 2;
            if (Q8) {
                float i0 = cinv[c], i1 = cinv[c + 1];
                if (r0 < M) {
                    char2 q; q.x = q8(acc[mt][nt][0] * i0); q.y = q8(acc[mt][nt][1] * i1);
                    *(char2*)&C8[(size_t)r0 * Ncol + c] = q;
                }
                if (r0 + 8 < M) {
                    char2 q; q.x = q8(acc[mt][nt][2] * i0); q.y = q8(acc[mt][nt][3] * i1);
                    *(char2*)&C8[(size_t)(r0 + 8) * Ncol + c] = q;
                }
            } else {
                if (r0 < M)
                    *(__half2*)&C[(size_t)r0 * Ncol + c] =
                        __float22half2_rn(make_float2(acc[mt][nt][0], acc[mt][nt][1]));
                if (r0 + 8 < M)
                    *(__half2*)&C[(size_t)(r0 + 8) * Ncol + c] =
                        __float22half2_rn(make_float2(acc[mt][nt][2], acc[mt][nt][3]));
            }
        }
    }
    const float* aSp = attS + blockIdx.x * 64;
    const float* aDp = attD + blockIdx.x * 64;
    float pS[2][2] = {{0.f, 0.f}, {0.f, 0.f}};
    float pD[2][2] = {{0.f, 0.f}, {0.f, 0.f}};
    #pragma unroll
    for (int mt = 0; mt < 2; mt++)
        #pragma unroll
        for (int nt = 0; nt < 4; nt++) {
            int cIH = wn + nt * 8 + tg * 2;
            float s0 = aSp[cIH], s1 = aSp[cIH + 1];
            float d0 = aDp[cIH], d1 = aDp[cIH + 1];
            pS[mt][0] += acc[mt][nt][0] * s0 + acc[mt][nt][1] * s1;
            pS[mt][1] += acc[mt][nt][2] * s0 + acc[mt][nt][3] * s1;
            pD[mt][0] += acc[mt][nt][0] * d0 + acc[mt][nt][1] * d1;
            pD[mt][1] += acc[mt][nt][2] * d0 + acc[mt][nt][3] * d1;
        }
    #pragma unroll
    for (int o = 1; o <= 2; o <<= 1) {
        #pragma unroll
        for (int mt = 0; mt < 2; mt++)
            #pragma unroll
            for (int h = 0; h < 2; h++) {
                pS[mt][h] += __shfl_xor_sync(0xFFFFFFFFu, pS[mt][h], o);
                pD[mt][h] += __shfl_xor_sync(0xFFFFFFFFu, pD[mt][h], o);
            }
    }
    float* fbuf = (float*)smem;
    __syncthreads();
    if (tg == 0) {
        int warpN = warpId >> 2;
        #pragma unroll
        for (int mt = 0; mt < 2; mt++)
            #pragma unroll
            for (int h = 0; h < 2; h++) {
                int row = wm + mt * 16 + h * 8 + g;
                fbuf[(warpN * 128 + row) * 2 + 0] = pS[mt][h];
                fbuf[(warpN * 128 + row) * 2 + 1] = pD[mt][h];
            }
    }
    __syncthreads();
    if (tid < 128) {
        int gr = bm0 + tid;
        if (gr < M) {
            asOut[(size_t)gr * asStr + blockIdx.x] = fbuf[tid * 2] + fbuf[(128 + tid) * 2];
            adOut[(size_t)gr * asStr + blockIdx.x] = fbuf[tid * 2 + 1] + fbuf[(128 + tid) * 2 + 1];
        }
    }
}

// ---------------- CSR build ----------------
__global__ void count_k(const int* __restrict__ adj) {
    int e = blockIdx.x * blockDim.x + threadIdx.x;
    if (e >= NET) return;
    int d = (e < NE) ? adj[NE + e] : (e - NE);
    atomicAdd(&g_deg[d], 1);
}
__global__ void scan1_k(int n) {
    __shared__ int sh[512];
    int i = blockIdx.x * 512 + threadIdx.x;
    int v = (i < n) ? g_deg[i] : 0;
    sh[threadIdx.x] = v;
    __syncthreads();
    for (int off = 1; off < 512; off <<= 1) {
        int t = (threadIdx.x >= (unsigned)off) ? sh[threadIdx.x - off] : 0;
        __syncthreads();
        sh[threadIdx.x] += t;
        __syncthreads();
    }
    if (i < n) g_row[i] = sh[threadIdx.x] - v;
    if (threadIdx.x == 511) g_bsums[blockIdx.x] = sh[511];
}
__global__ void scan23_k(int n) {
    __shared__ int soff[4];
    __shared__ int offsh;
    int tid = threadIdx.x;
    if (tid < 128) {
        int v = (tid < blockIdx.x) ? g_bsums[tid] : 0;
        v = warpSumI(v);
        if ((tid & 31) == 0) soff[tid >> 5] = v;
    }
    __syncthreads();
    if (tid == 0) offsh = soff[0] + soff[1] + soff[2] + soff[3];
    __syncthreads();
    int i = blockIdx.x * 512 + tid;
    if (i < n) {
        int r = g_row[i] + offsh;
        g_row[i] = r;
        g_cursor[i] = r;
    }
    if (i == 0) g_row[n] = NET;
}
__global__ void scatter_k(const int* __restrict__ adj) {
    int e = blockIdx.x * blockDim.x + threadIdx.x;
    if (e >= NET) return;
    int s, d;
    if (e < NE) { s = adj[e]; d = adj[NE + e]; }
    else        { s = e - NE; d = s; }
    int pos = atomicAdd(&g_cursor[d], 1);
    g_csr[pos] = s;
}

// ---------------- layer-1 aggregate: persistent blocked, int8 gather, fused denom ----------------
#define AGG_GRID 592
#define AGG_WARPS (AGG_GRID * 8)        // 4736
#define NODES_PER_WARP ((NN + AGG_WARPS - 1) / AGG_WARPS)   // 11
__global__ __launch_bounds__(256) void agg1_k(const float* __restrict__ b1) {
    int w = (blockIdx.x * blockDim.x + threadIdx.x) >> 5;
    int lane = threadIdx.x & 31;
    const uint2* h1p = (const uint2*)g_h1q;      // 32 uint2 per 256B row
    int hh = lane >> 3;
    int c0 = lane * 8;

    float scl[8];
    #pragma unroll
    for (int j = 0; j < 8; j++) scl[j] = g_cscale[c0 + j];

    int n0 = w * NODES_PER_WARP;
    int n1 = min(n0 + NODES_PER_WARP, NN);
    for (int n = n0; n < n1; n++) {
        int beg = g_row[n], end = g_row[n + 1];
        float myAd = g_ad1[n * 4 + hh];

        float den = 0.f;
        float a0 = 0.f, a1 = 0.f, a2 = 0.f, a3 = 0.f, a4 = 0.f, a5 = 0.f, a6 = 0.f, a7 = 0.f;
        int e = beg;
        for (; e + 4 <= end; e += 4) {
            int s0 = g_csr[e], s1 = g_csr[e + 1], s2 = g_csr[e + 2], s3 = g_csr[e + 3];
            float w0 = lrelu(g_as1[s0 * 4 + hh] + myAd);
            float w1 = lrelu(g_as1[s1 * 4 + hh] + myAd);
            float w2 = lrelu(g_as1[s2 * 4 + hh] + myAd);
            float w3 = lrelu(g_as1[s3 * 4 + hh] + myAd);
            uint2 r0 = ldcg8(h1p + (size_t)s0 * 32 + lane);
            uint2 r1 = ldcg8(h1p + (size_t)s1 * 32 + lane);
            uint2 r2 = ldcg8(h1p + (size_t)s2 * 32 + lane);
            uint2 r3 = ldcg8(h1p + (size_t)s3 * 32 + lane);
            w0 = __expf(w0); w1 = __expf(w1); w2 = __expf(w2); w3 = __expf(w3);
            den += (w0 + w1) + (w2 + w3);
            #pragma unroll
            for (int q = 0; q < 4; q++) {
                uint2 rr = (q == 0) ? r0 : (q == 1) ? r1 : (q == 2) ? r2 : r3;
                float ww = (q == 0) ? w0 : (q == 1) ? w1 : (q == 2) ? w2 : w3;
                a0 += ww * i8f<0>(rr.x); a1 += ww * i8f<1>(rr.x);
                a2 += ww * i8f<2>(rr.x); a3 += ww * i8f<3>(rr.x);
                a4 += ww * i8f<0>(rr.y); a5 += ww * i8f<1>(rr.y);
                a6 += ww * i8f<2>(rr.y); a7 += ww * i8f<3>(rr.y);
            }
        }
        for (; e < end; e++) {
            int src = g_csr[e];
            float ww = __expf(lrelu(g_as1[src * 4 + hh] + myAd));
            den += ww;
            uint2 rr = ldcg8(h1p + (size_t)src * 32 + lane);
            a0 += ww * i8f<0>(rr.x); a1 += ww * i8f<1>(rr.x);
            a2 += ww * i8f<2>(rr.x); a3 += ww * i8f<3>(rr.x);
            a4 += ww * i8f<0>(rr.y); a5 += ww * i8f<1>(rr.y);
            a6 += ww * i8f<2>(rr.y); a7 += ww * i8f<3>(rr.y);
        }
        float inv = 1.f / den;
        float4 bb0 = *(const float4*)&b1[c0];
        float4 bb1 = *(const float4*)&b1[c0 + 4];
        float o[8] = {a0 * scl[0] * inv + bb0.x, a1 * scl[1] * inv + bb0.y,
                      a2 * scl[2] * inv + bb0.z, a3 * scl[3] * inv + bb0.w,
                      a4 * scl[4] * inv + bb1.x, a5 * scl[5] * inv + bb1.y,
                      a6 * scl[6] * inv + bb1.z, a7 * scl[7] * inv + bb1.w};
        #pragma unroll
        for (int j = 0; j < 8; j++) o[j] = (o[j] > 0.f) ? o[j] : (__expf(o[j]) - 1.f);
        uint4 packed;
        *(__half2*)&packed.x = __float22half2_rn(make_float2(o[0], o[1]));
        *(__half2*)&packed.y = __float22half2_rn(make_float2(o[2], o[3]));
        *(__half2*)&packed.z = __float22half2_rn(make_float2(o[4], o[5]));
        *(__half2*)&packed.w = __float22half2_rn(make_float2(o[6], o[7]));
        *(uint4*)&g_heluh[(size_t)n * HHID + c0] = packed;
    }
}

// ---------------- layer-2 aggregate: persistent blocked, fused denom + log_softmax ----------------
__global__ __launch_bounds__(256) void agg2_k(const float* __restrict__ b2, float* __restrict__ out) {
    int w = (blockIdx.x * blockDim.x + threadIdx.x) >> 5;
    int lane = threadIdx.x & 31;
    const unsigned* h2p = (const unsigned*)g_h2h;

    int n0 = w * NODES_PER_WARP;
    int n1 = min(n0 + NODES_PER_WARP, NN);
    for (int n = n0; n < n1; n++) {
        int beg = g_row[n], end = g_row[n + 1];
        float adv = g_ad2[n];

        float den = 0.f, acc0 = 0.f, acc1 = 0.f;
        int e = beg;
        for (; e + 4 <= end; e += 4) {
            int s0 = g_csr[e], s1 = g_csr[e + 1], s2 = g_csr[e + 2], s3 = g_csr[e + 3];
            float w0 = lrelu(g_as2[s0] + adv);
            float w1 = lrelu(g_as2[s1] + adv);
            float w2 = lrelu(g_as2[s2] + adv);
            float w3 = lrelu(g_as2[s3] + adv);
            unsigned u0 = ldcg4(h2p + (size_t)s0 * 32 + lane);
            unsigned u1 = ldcg4(h2p + (size_t)s1 * 32 + lane);
            unsigned u2 = ldcg4(h2p + (size_t)s2 * 32 + lane);
            unsigned u3 = ldcg4(h2p + (size_t)s3 * 32 + lane);
            float2 v0 = __half22float2(*(__half2*)&u0);
            float2 v1 = __half22float2(*(__half2*)&u1);
            float2 v2 = __half22float2(*(__half2*)&u2);
            float2 v3 = __half22float2(*(__half2*)&u3);
            w0 = __expf(w0); w1 = __expf(w1); w2 = __expf(w2); w3 = __expf(w3);
            den += (w0 + w1) + (w2 + w3);
            acc0 += w0 * v0.x + w1 * v1.x + w2 * v2.x + w3 * v3.x;
            acc1 += w0 * v0.y + w1 * v1.y + w2 * v2.y + w3 * v3.y;
        }
        for (; e < end; e++) {
            int src = g_csr[e];
            float ww = __expf(lrelu(g_as2[src] + adv));
            den += ww;
            unsigned u = ldcg4(h2p + (size_t)src * 32 + lane);
            float2 v = __half22float2(*(__half2*)&u);
            acc0 += ww * v.x; acc1 += ww * v.y;
        }
        float inv = 1.f / den;
        acc0 = acc0 * inv + b2[lane * 2];
        acc1 = acc1 * inv + b2[lane * 2 + 1];

        float M = warpMax(fmaxf(acc0, acc1));
        float S = warpSum(__expf(acc0 - M) + __expf(acc1 - M));
        float L = M + __logf(S);
        out[(size_t)n * OUTC + lane * 2]     = acc0 - L;
        out[(size_t)n * OUTC + lane * 2 + 1] = acc1 - L;
    }
}

// ---------------- launch ----------------
extern "C" void kernel_launch(void* const* d_in, const int* in_sizes, int n_in,
                              void* d_out, int out_size) {
    const float* x        = (const float*)d_in[0];
    const int*   adj      = (const int*)d_in[1];
    const float* W1       = (const float*)d_in[2];
    const float* att_src1 = (const float*)d_in[3];
    const float* att_dst1 = (const float*)d_in[4];
    const float* b1       = (const float*)d_in[5];
    const float* W2       = (const float*)d_in[6];
    const float* att_src2 = (const float*)d_in[7];
    const float* att_dst2 = (const float*)d_in[8];
    const float* b2       = (const float*)d_in[9];
    float* out = (float*)d_out;

    __half *p_xh, *p_w1t, *p_w2t, *p_heluh, *p_h2h;
    char *p_h1q;
    float *p_as1, *p_ad1, *p_as2, *p_ad2, *p_cinv;
    int *p_deg;
    cudaGetSymbolAddress((void**)&p_xh, g_xh);
    cudaGetSymbolAddress((void**)&p_w1t, g_w1t);
    cudaGetSymbolAddress((void**)&p_w2t, g_w2t);
    cudaGetSymbolAddress((void**)&p_h1q, g_h1q);
    cudaGetSymbolAddress((void**)&p_cinv, g_cinv);
    cudaGetSymbolAddress((void**)&p_heluh, g_heluh);
    cudaGetSymbolAddress((void**)&p_h2h, g_h2h);
    cudaGetSymbolAddress((void**)&p_as1, g_as1);
    cudaGetSymbolAddress((void**)&p_ad1, g_ad1);
    cudaGetSymbolAddress((void**)&p_as2, g_as2);
    cudaGetSymbolAddress((void**)&p_ad2, g_ad2);
    cudaGetSymbolAddress((void**)&p_deg, g_deg);

    static cudaStream_t s1 = nullptr;
    static cudaEvent_t evFork = nullptr, evJoin = nullptr;
    if (!s1) {
        cudaFuncSetAttribute(gemm_h16_k<true>, cudaFuncAttributeMaxDynamicSharedMemorySize, GEMM_SMEM);
        cudaFuncSetAttribute(gemm_h16_k<false>, cudaFuncAttributeMaxDynamicSharedMemorySize, GEMM_SMEM);
        cudaStreamCreateWithFlags(&s1, cudaStreamNonBlocking);
        cudaEventCreateWithFlags(&evFork, cudaEventDisableTiming);
        cudaEventCreateWithFlags(&evJoin, cudaEventDisableTiming);
    }

    const int edgeBlocks = (NET + 255) / 256;
    const int scanBlocks = (NN + 511) / 512;         // 98

    cudaEventRecord(evFork, 0);
    cudaStreamWaitEvent(s1, evFork, 0);

    // main: CSR build; side: cvt + gemm1(int8 out)
    cudaMemsetAsync(p_deg, 0, NN * sizeof(int), 0);
    cvt_k<<<CVT_XBLK + 21, 256, 0, s1>>>(x, W1, W2);                     // k1 (side)
    count_k<<<edgeBlocks, 256>>>(adj);                                   // k2 (main)
    scan1_k<<<scanBlocks, 512>>>(NN);                                    // k3 (main)
    gemm_h16_k<true><<<dim3(HHID / TBN, (NN + TBM - 1) / TBM), 256, GEMM_SMEM, s1>>>(  // k4 (profiled)
        p_xh, p_w1t, nullptr, p_h1q, p_cinv,
        p_as1, p_ad1, att_src1, att_dst1, NH, NN, HHID, FIN);
    cudaEventRecord(evJoin, s1);

    scan23_k<<<scanBlocks, 512>>>(NN);                                   // k5
    scatter_k<<<edgeBlocks, 256>>>(adj);                                 // k6

    cudaStreamWaitEvent(0, evJoin, 0);
    agg1_k<<<AGG_GRID, 256>>>(b1);                                       // k7
    gemm_h16_k<false><<<dim3(OUTC / TBN, (NN + TBM - 1) / TBM), 256, GEMM_SMEM>>>(     // k8
        p_heluh, p_w2t, p_h2h, nullptr, nullptr,
        p_as2, p_ad2, att_src2, att_dst2, 1, NN, OUTC, HHID);
    agg2_k<<<AGG_GRID, 256>>>(b2, out);                                  // k9
}

// round 16
// speedup vs baseline: 1.0761x; 1.0761x over previous
#include <cuda_runtime.h>
#include <cuda_fp16.h>
#include <math.h>

#define NN    50000
#define FIN   256
#define HHID  256
#define NH    4
#define HID   64
#define OUTC  64
#define NE    800000
#define NET   (NE + NN)
#define SLOPE 0.2f
#define NSPLIT 25088     // agg1/gemm2 pipeline split (multiple of 128)

// ---------------- device scratch ----------------
__device__ __half g_xh[NN * FIN];
__device__ __half g_w1t[HHID * FIN];
__device__ __half g_w2t[OUTC * HHID];
__device__ __half g_h1h[NN * HHID];
__device__ __half g_heluh[NN * HHID];
__device__ __half g_h2h[NN * OUTC];
__device__ float g_as1[NN * NH];
__device__ float g_ad1[NN * NH];
__device__ float g_as2[NN];
__device__ float g_ad2[NN];
__device__ __align__(16) int g_deg[NN];
__device__ __align__(16) int g_cursor[NN];
__device__ __align__(16) int g_row[NN + 4];
__device__ int g_csr[NET];
__device__ int g_bsums[128];

// ---------------- helpers ----------------
__device__ __forceinline__ float warpSum(float v) {
    #pragma unroll
    for (int o = 16; o; o >>= 1) v += __shfl_xor_sync(0xFFFFFFFFu, v, o);
    return v;
}
__device__ __forceinline__ int warpSumI(int v) {
    #pragma unroll
    for (int o = 16; o; o >>= 1) v += __shfl_xor_sync(0xFFFFFFFFu, v, o);
    return v;
}
__device__ __forceinline__ float warpMax(float v) {
    #pragma unroll
    for (int o = 16; o; o >>= 1) v = fmaxf(v, __shfl_xor_sync(0xFFFFFFFFu, v, o));
    return v;
}
__device__ __forceinline__ float lrelu(float a) { return a > 0.f ? a : SLOPE * a; }
__device__ __forceinline__ uint4 ldcg16(const uint4* p) {
    uint4 v;
    asm volatile("ld.global.cg.v4.u32 {%0,%1,%2,%3}, [%4];"
                 : "=r"(v.x), "=r"(v.y), "=r"(v.z), "=r"(v.w) : "l"(p));
    return v;
}
__device__ __forceinline__ unsigned ldcg4(const unsigned* p) {
    unsigned v;
    asm volatile("ld.global.cg.u32 %0, [%1];" : "=r"(v) : "l"(p));
    return v;
}

// ---------------- conversions, split across streams ----------------
#define XHALF (NN * FIN / 2)          // 6.4M floats
#define XBLK  (XHALF / 1024)          // 6250 blocks per half
// cvtA: first half of x + both weight transposes (side stream)
__global__ void cvtA_k(const float* __restrict__ x, const float* __restrict__ W1,
                       const float* __restrict__ W2) {
    int b = blockIdx.x;
    if (b < XBLK) {
        int i = (b * 256 + threadIdx.x) * 4;
        float4 v = *(const float4*)&x[i];
        *(__half2*)&g_xh[i]     = __float22half2_rn(make_float2(v.x, v.y));
        *(__half2*)&g_xh[i + 2] = __float22half2_rn(make_float2(v.z, v.w));
    } else if (b < XBLK + 16) {
        int base = (b - XBLK) * 4096 + threadIdx.x;
        #pragma unroll
        for (int it = 0; it < 16; it++) {
            int idx = base + it * 256;
            int k = idx >> 8, n = idx & 255;
            g_w1t[n * 256 + k] = __float2half(W1[idx]);
        }
    } else {
        int base = (b - XBLK - 16) * 4096 + threadIdx.x;
        #pragma unroll
        for (int it = 0; it < 16; it++) {
            int idx = base + it * 256;
            int k = idx >> 6, n = idx & 63;
            g_w2t[n * 256 + k] = __float2half(W2[idx]);
        }
    }
}
// cvtB: second half of x (main stream)
__global__ void cvtB_k(const float* __restrict__ x) {
    int i = XHALF + (blockIdx.x * 256 + threadIdx.x) * 4;
    float4 v = *(const float4*)&x[i];
    *(__half2*)&g_xh[i]     = __float22half2_rn(make_float2(v.x, v.y));
    *(__half2*)&g_xh[i + 2] = __float22half2_rn(make_float2(v.z, v.w));
}

// ---------------- fp16 GEMM, cp.async + ldmatrix, fused attention epilogue ----------------
#define TBM 128
#define TBN 64
#define TBK 64
#define AST 72
#define BST 72
#define GEMM_SMEM ((2 * TBM * AST + 2 * TBN * BST) * 2)

__device__ __forceinline__ void cp16(unsigned dst, const void* src, int sz) {
    asm volatile("cp.async.cg.shared.global [%0], [%1], 16, %2;\n"
                 :: "r"(dst), "l"(src), "r"(sz));
}
__device__ __forceinline__ void ldsm4(unsigned& r0, unsigned& r1, unsigned& r2, unsigned& r3,
                                      unsigned addr) {
    asm volatile("ldmatrix.sync.aligned.m8n8.x4.shared.b16 {%0,%1,%2,%3}, [%4];"
                 : "=r"(r0), "=r"(r1), "=r"(r2), "=r"(r3) : "r"(addr));
}
#define MMA_H16(accv, a0, a1, a2, a3, b0, b1)                                    \
    asm volatile("mma.sync.aligned.m16n8k16.row.col.f32.f16.f16.f32 "            \
                 "{%0,%1,%2,%3}, {%4,%5,%6,%7}, {%8,%9}, {%0,%1,%2,%3};"         \
                 : "+f"(accv[0]), "+f"(accv[1]), "+f"(accv[2]), "+f"(accv[3])    \
                 : "r"(a0), "r"(a1), "r"(a2), "r"(a3), "r"(b0), "r"(b1))

__global__ __launch_bounds__(256, 4) void gemm_h16_k(
        const __half* __restrict__ A, const __half* __restrict__ Bt,
        __half* __restrict__ C,
        float* __restrict__ asOut, float* __restrict__ adOut,
        const float* __restrict__ attS, const float* __restrict__ attD,
        int asStr, int M, int Ncol, int K) {
    extern __shared__ char smem[];
    __half* As = (__half*)smem;
    __half* Bs = (__half*)smem + 2 * TBM * AST;
    const unsigned As_u = (unsigned)__cvta_generic_to_shared(As);
    const unsigned Bs_u = (unsigned)__cvta_generic_to_shared(Bs);

    const int tid = threadIdx.x;
    const int bm0 = blockIdx.y * TBM;
    const int bn0 = blockIdx.x * TBN;
    const int warpId = tid >> 5;
    const int lane = tid & 31;
    const int g  = lane >> 2;
    const int tg = lane & 3;
    const int wm = (warpId & 3) * 32;
    const int wn = (warpId >> 2) * 32;

    const int aRow = lane & 15;
    const int aCol = (lane >> 4) * 8;
    const int bRowP = ((lane >> 4) * 8) + (lane & 7);
    const int bCol = ((lane >> 3) & 1) * 8;

    float acc[2][4][4];
    #pragma unroll
    for (int i = 0; i < 2; i++)
        #pragma unroll
        for (int j = 0; j < 4; j++)
            #pragma unroll
            for (int r = 0; r < 4; r++) acc[i][j][r] = 0.f;

    const int KT = K / TBK;

    auto loadTile = [&](int kt, int buf) {
        int k0 = kt * TBK;
        unsigned aBase = As_u + (unsigned)buf * TBM * AST * 2;
        unsigned bBase = Bs_u + (unsigned)buf * TBN * BST * 2;
        #pragma unroll
        for (int it = 0; it < 4; it++) {
            int idx = tid + it * 256;
            int m = idx >> 3, ch = idx & 7;
            const __half* src = A + (size_t)(bm0 + m) * K + k0 + ch * 8;
            int sz = (bm0 + m < M) ? 16 : 0;
            cp16(aBase + (unsigned)(m * AST + ch * 8) * 2, src, sz);
        }
        #pragma unroll
        for (int it = 0; it < 2; it++) {
            int idx = tid + it * 256;
            int n = idx >> 3, ch = idx & 7;
            const __half* src = Bt + (size_t)(bn0 + n) * K + k0 + ch * 8;
            cp16(bBase + (unsigned)(n * BST + ch * 8) * 2, src, 16);
        }
        asm volatile("cp.async.commit_group;\n");
    };

    loadTile(0, 0);

    for (int kt = 0; kt < KT; kt++) {
        if (kt + 1 < KT) {
            loadTile(kt + 1, (kt + 1) & 1);
            asm volatile("cp.async.wait_group 1;\n");
        } else {
            asm volatile("cp.async.wait_group 0;\n");
        }
        __syncthreads();

        unsigned AbU = As_u + (unsigned)(kt & 1) * TBM * AST * 2;
        unsigned BbU = Bs_u + (unsigned)(kt & 1) * TBN * BST * 2;

        #pragma unroll
        for (int kc = 0; kc < TBK; kc += 16) {
            unsigned af[2][4], bf[4][2];
            #pragma unroll
            for (int mt = 0; mt < 2; mt++) {
                unsigned addr = AbU + (unsigned)((wm + mt * 16 + aRow) * AST + kc + aCol) * 2;
                ldsm4(af[mt][0], af[mt][1], af[mt][2], af[mt][3], addr);
            }
            #pragma unroll
            for (int p = 0; p < 2; p++) {
                unsigned addr = BbU + (unsigned)((wn + p * 16 + bRowP) * BST + kc + bCol) * 2;
                ldsm4(bf[2 * p][0], bf[2 * p][1], bf[2 * p + 1][0], bf[2 * p + 1][1], addr);
            }
            #pragma unroll
            for (int mt = 0; mt < 2; mt++)
                #pragma unroll
                for (int nt = 0; nt < 4; nt++)
                    MMA_H16(acc[mt][nt], af[mt][0], af[mt][1], af[mt][2], af[mt][3],
                            bf[nt][0], bf[nt][1]);
        }
        __syncthreads();
    }

    #pragma unroll
    for (int mt = 0; mt < 2; mt++) {
        int r0 = bm0 + wm + mt * 16 + g;
        #pragma unroll
        for (int nt = 0; nt < 4; nt++) {
            int c = bn0 + wn + nt * 8 + tg * 2;
            if (r0 < M)
                *(__half2*)&C[(size_t)r0 * Ncol + c] =
                    __float22half2_rn(make_float2(acc[mt][nt][0], acc[mt][nt][1]));
            if (r0 + 8 < M)
                *(__half2*)&C[(size_t)(r0 + 8) * Ncol + c] =
                    __float22half2_rn(make_float2(acc[mt][nt][2], acc[mt][nt][3]));
        }
    }
    const float* aSp = attS + blockIdx.x * 64;
    const float* aDp = attD + blockIdx.x * 64;
    float pS[2][2] = {{0.f, 0.f}, {0.f, 0.f}};
    float pD[2][2] = {{0.f, 0.f}, {0.f, 0.f}};
    #pragma unroll
    for (int mt = 0; mt < 2; mt++)
        #pragma unroll
        for (int nt = 0; nt < 4; nt++) {
            int cIH = wn + nt * 8 + tg * 2;
            float s0 = aSp[cIH], s1 = aSp[cIH + 1];
            float d0 = aDp[cIH], d1 = aDp[cIH + 1];
            pS[mt][0] += acc[mt][nt][0] * s0 + acc[mt][nt][1] * s1;
            pS[mt][1] += acc[mt][nt][2] * s0 + acc[mt][nt][3] * s1;
            pD[mt][0] += acc[mt][nt][0] * d0 + acc[mt][nt][1] * d1;
            pD[mt][1] += acc[mt][nt][2] * d0 + acc[mt][nt][3] * d1;
        }
    #pragma unroll
    for (int o = 1; o <= 2; o <<= 1) {
        #pragma unroll
        for (int mt = 0; mt < 2; mt++)
            #pragma unroll
            for (int h = 0; h < 2; h++) {
                pS[mt][h] += __shfl_xor_sync(0xFFFFFFFFu, pS[mt][h], o);
                pD[mt][h] += __shfl_xor_sync(0xFFFFFFFFu, pD[mt][h], o);
            }
    }
    float* fbuf = (float*)smem;
    __syncthreads();
    if (tg == 0) {
        int warpN = warpId >> 2;
        #pragma unroll
        for (int mt = 0; mt < 2; mt++)
            #pragma unroll
            for (int h = 0; h < 2; h++) {
                int row = wm + mt * 16 + h * 8 + g;
                fbuf[(warpN * 128 + row) * 2 + 0] = pS[mt][h];
                fbuf[(warpN * 128 + row) * 2 + 1] = pD[mt][h];
            }
    }
    __syncthreads();
    if (tid < 128) {
        int gr = bm0 + tid;
        if (gr < M) {
            asOut[(size_t)gr * asStr + blockIdx.x] = fbuf[tid * 2] + fbuf[(128 + tid) * 2];
            adOut[(size_t)gr * asStr + blockIdx.x] = fbuf[tid * 2 + 1] + fbuf[(128 + tid) * 2 + 1];
        }
    }
}

// ---------------- CSR build ----------------
__global__ void count_k(const int* __restrict__ adj) {
    int e = blockIdx.x * blockDim.x + threadIdx.x;
    if (e >= NET) return;
    int d = (e < NE) ? adj[NE + e] : (e - NE);
    atomicAdd(&g_deg[d], 1);
}
__global__ void scan1_k(int n) {
    __shared__ int sh[512];
    int i = blockIdx.x * 512 + threadIdx.x;
    int v = (i < n) ? g_deg[i] : 0;
    sh[threadIdx.x] = v;
    __syncthreads();
    for (int off = 1; off < 512; off <<= 1) {
        int t = (threadIdx.x >= (unsigned)off) ? sh[threadIdx.x - off] : 0;
        __syncthreads();
        sh[threadIdx.x] += t;
        __syncthreads();
    }
    if (i < n) g_row[i] = sh[threadIdx.x] - v;
    if (threadIdx.x == 511) g_bsums[blockIdx.x] = sh[511];
}
__global__ void scan23_k(int n) {
    __shared__ int soff[4];
    __shared__ int offsh;
    int tid = threadIdx.x;
    if (tid < 128) {
        int v = (tid < blockIdx.x) ? g_bsums[tid] : 0;
        v = warpSumI(v);
        if ((tid & 31) == 0) soff[tid >> 5] = v;
    }
    __syncthreads();
    if (tid == 0) offsh = soff[0] + soff[1] + soff[2] + soff[3];
    __syncthreads();
    int i = blockIdx.x * 512 + tid;
    if (i < n) {
        int r = g_row[i] + offsh;
        g_row[i] = r;
        g_cursor[i] = r;
    }
    if (i == 0) g_row[n] = NET;
}
__global__ void scatter_k(const int* __restrict__ adj) {
    int e = blockIdx.x * blockDim.x + threadIdx.x;
    if (e >= NET) return;
    int s, d;
    if (e < NE) { s = adj[e]; d = adj[NE + e]; }
    else        { s = e - NE; d = s; }
    int pos = atomicAdd(&g_cursor[d], 1);
    g_csr[pos] = s;
}

// ---------------- layer-1 aggregate: persistent blocked range, fused denom ----------------
#define AGG_GRID 592
#define AGG_WARPS (AGG_GRID * 8)        // 4736
__global__ __launch_bounds__(256) void agg1_k(const float* __restrict__ b1, int nBase, int nEnd) {
    int w = (blockIdx.x * blockDim.x + threadIdx.x) >> 5;
    int lane = threadIdx.x & 31;
    const uint4* h1p = (const uint4*)g_h1h;
    int hh = lane >> 3;

    int range = nEnd - nBase;
    int npw = (range + AGG_WARPS - 1) / AGG_WARPS;
    int n0 = nBase + w * npw;
    int n1 = min(n0 + npw, nEnd);
    for (int n = n0; n < n1; n++) {
        int beg = g_row[n], end = g_row[n + 1];
        float myAd = g_ad1[n * 4 + hh];

        float den = 0.f;
        float a0 = 0.f, a1 = 0.f, a2 = 0.f, a3 = 0.f, a4 = 0.f, a5 = 0.f, a6 = 0.f, a7 = 0.f;
        int e = beg;
        for (; e + 4 <= end; e += 4) {
            int s0 = g_csr[e], s1 = g_csr[e + 1], s2 = g_csr[e + 2], s3 = g_csr[e + 3];
            float w0 = lrelu(g_as1[s0 * 4 + hh] + myAd);
            float w1 = lrelu(g_as1[s1 * 4 + hh] + myAd);
            float w2 = lrelu(g_as1[s2 * 4 + hh] + myAd);
            float w3 = lrelu(g_as1[s3 * 4 + hh] + myAd);
            uint4 r0 = ldcg16(h1p + (size_t)s0 * 32 + lane);
            uint4 r1 = ldcg16(h1p + (size_t)s1 * 32 + lane);
            uint4 r2 = ldcg16(h1p + (size_t)s2 * 32 + lane);
            uint4 r3 = ldcg16(h1p + (size_t)s3 * 32 + lane);
            w0 = __expf(w0); w1 = __expf(w1); w2 = __expf(w2); w3 = __expf(w3);
            den += (w0 + w1) + (w2 + w3);
            #pragma unroll
            for (int q = 0; q < 4; q++) {
                uint4 rr = (q == 0) ? r0 : (q == 1) ? r1 : (q == 2) ? r2 : r3;
                float ww = (q == 0) ? w0 : (q == 1) ? w1 : (q == 2) ? w2 : w3;
                float2 p0 = __half22float2(*(__half2*)&rr.x);
                float2 p1 = __half22float2(*(__half2*)&rr.y);
                float2 p2 = __half22float2(*(__half2*)&rr.z);
                float2 p3 = __half22float2(*(__half2*)&rr.w);
                a0 += ww * p0.x; a1 += ww * p0.y; a2 += ww * p1.x; a3 += ww * p1.y;
                a4 += ww * p2.x; a5 += ww * p2.y; a6 += ww * p3.x; a7 += ww * p3.y;
            }
        }
        for (; e < end; e++) {
            int src = g_csr[e];
            float w = __expf(lrelu(g_as1[src * 4 + hh] + myAd));
            den += w;
            uint4 raw = ldcg16(h1p + (size_t)src * 32 + lane);
            float2 p0 = __half22float2(*(__half2*)&raw.x);
            float2 p1 = __half22float2(*(__half2*)&raw.y);
            float2 p2 = __half22float2(*(__half2*)&raw.z);
            float2 p3 = __half22float2(*(__half2*)&raw.w);
            a0 += w * p0.x; a1 += w * p0.y; a2 += w * p1.x; a3 += w * p1.y;
            a4 += w * p2.x; a5 += w * p2.y; a6 += w * p3.x; a7 += w * p3.y;
        }
        float inv = 1.f / den;
        int c0 = lane * 8;
        float4 bb0 = *(const float4*)&b1[c0];
        float4 bb1 = *(const float4*)&b1[c0 + 4];
        float o[8] = {a0 * inv + bb0.x, a1 * inv + bb0.y, a2 * inv + bb0.z, a3 * inv + bb0.w,
                      a4 * inv + bb1.x, a5 * inv + bb1.y, a6 * inv + bb1.z, a7 * inv + bb1.w};
        #pragma unroll
        for (int j = 0; j < 8; j++) o[j] = (o[j] > 0.f) ? o[j] : (__expf(o[j]) - 1.f);
        uint4 packed;
        *(__half2*)&packed.x = __float22half2_rn(make_float2(o[0], o[1]));
        *(__half2*)&packed.y = __float22half2_rn(make_float2(o[2], o[3]));
        *(__half2*)&packed.z = __float22half2_rn(make_float2(o[4], o[5]));
        *(__half2*)&packed.w = __float22half2_rn(make_float2(o[6], o[7]));
        *(uint4*)&g_heluh[(size_t)n * HHID + c0] = packed;
    }
}

// ---------------- layer-2 aggregate: persistent blocked, fused denom + log_softmax ----------------
#define NODES_PER_WARP ((NN + AGG_WARPS - 1) / AGG_WARPS)   // 11
__global__ __launch_bounds__(256) void agg2_k(const float* __restrict__ b2, float* __restrict__ out) {
    int w = (blockIdx.x * blockDim.x + threadIdx.x) >> 5;
    int lane = threadIdx.x & 31;
    const unsigned* h2p = (const unsigned*)g_h2h;

    int n0 = w * NODES_PER_WARP;
    int n1 = min(n0 + NODES_PER_WARP, NN);
    for (int n = n0; n < n1; n++) {
        int beg = g_row[n], end = g_row[n + 1];
        float adv = g_ad2[n];

        float den = 0.f, acc0 = 0.f, acc1 = 0.f;
        int e = beg;
        for (; e + 4 <= end; e += 4) {
            int s0 = g_csr[e], s1 = g_csr[e + 1], s2 = g_csr[e + 2], s3 = g_csr[e + 3];
            float w0 = lrelu(g_as2[s0] + adv);
            float w1 = lrelu(g_as2[s1] + adv);
            float w2 = lrelu(g_as2[s2] + adv);
            float w3 = lrelu(g_as2[s3] + adv);
            unsigned u0 = ldcg4(h2p + (size_t)s0 * 32 + lane);
            unsigned u1 = ldcg4(h2p + (size_t)s1 * 32 + lane);
            unsigned u2 = ldcg4(h2p + (size_t)s2 * 32 + lane);
            unsigned u3 = ldcg4(h2p + (size_t)s3 * 32 + lane);
            float2 v0 = __half22float2(*(__half2*)&u0);
            float2 v1 = __half22float2(*(__half2*)&u1);
            float2 v2 = __half22float2(*(__half2*)&u2);
            float2 v3 = __half22float2(*(__half2*)&u3);
            w0 = __expf(w0); w1 = __expf(w1); w2 = __expf(w2); w3 = __expf(w3);
            den += (w0 + w1) + (w2 + w3);
            acc0 += w0 * v0.x + w1 * v1.x + w2 * v2.x + w3 * v3.x;
            acc1 += w0 * v0.y + w1 * v1.y + w2 * v2.y + w3 * v3.y;
        }
        for (; e < end; e++) {
            int src = g_csr[e];
            float w = __expf(lrelu(g_as2[src] + adv));
            den += w;
            unsigned u = ldcg4(h2p + (size_t)src * 32 + lane);
            float2 v = __half22float2(*(__half2*)&u);
            acc0 += w * v.x; acc1 += w * v.y;
        }
        float inv = 1.f / den;
        acc0 = acc0 * inv + b2[lane * 2];
        acc1 = acc1 * inv + b2[lane * 2 + 1];

        float M = warpMax(fmaxf(acc0, acc1));
        float S = warpSum(__expf(acc0 - M) + __expf(acc1 - M));
        float L = M + __logf(S);
        out[(size_t)n * OUTC + lane * 2]     = acc0 - L;
        out[(size_t)n * OUTC + lane * 2 + 1] = acc1 - L;
    }
}

// ---------------- launch ----------------
extern "C" void kernel_launch(void* const* d_in, const int* in_sizes, int n_in,
                              void* d_out, int out_size) {
    const float* x        = (const float*)d_in[0];
    const int*   adj      = (const int*)d_in[1];
    const float* W1       = (const float*)d_in[2];
    const float* att_src1 = (const float*)d_in[3];
    const float* att_dst1 = (const float*)d_in[4];
    const float* b1       = (const float*)d_in[5];
    const float* W2       = (const float*)d_in[6];
    const float* att_src2 = (const float*)d_in[7];
    const float* att_dst2 = (const float*)d_in[8];
    const float* b2       = (const float*)d_in[9];
    float* out = (float*)d_out;

    __half *p_xh, *p_w1t, *p_w2t, *p_h1h, *p_heluh, *p_h2h;
    float *p_as1, *p_ad1, *p_as2, *p_ad2;
    int *p_deg;
    cudaGetSymbolAddress((void**)&p_xh, g_xh);
    cudaGetSymbolAddress((void**)&p_w1t, g_w1t);
    cudaGetSymbolAddress((void**)&p_w2t, g_w2t);
    cudaGetSymbolAddress((void**)&p_h1h, g_h1h);
    cudaGetSymbolAddress((void**)&p_heluh, g_heluh);
    cudaGetSymbolAddress((void**)&p_h2h, g_h2h);
    cudaGetSymbolAddress((void**)&p_as1, g_as1);
    cudaGetSymbolAddress((void**)&p_ad1, g_ad1);
    cudaGetSymbolAddress((void**)&p_as2, g_as2);
    cudaGetSymbolAddress((void**)&p_ad2, g_ad2);
    cudaGetSymbolAddress((void**)&p_deg, g_deg);

    static cudaStream_t s1 = nullptr;
    static cudaEvent_t evFork = nullptr, evXB = nullptr, evJoin = nullptr,
                       evA1a = nullptr, evG2a = nullptr;
    if (!s1) {
        cudaFuncSetAttribute(gemm_h16_k, cudaFuncAttributeMaxDynamicSharedMemorySize, GEMM_SMEM);
        cudaStreamCreateWithFlags(&s1, cudaStreamNonBlocking);
        cudaEventCreateWithFlags(&evFork, cudaEventDisableTiming);
        cudaEventCreateWithFlags(&evXB, cudaEventDisableTiming);
        cudaEventCreateWithFlags(&evJoin, cudaEventDisableTiming);
        cudaEventCreateWithFlags(&evA1a, cudaEventDisableTiming);
        cudaEventCreateWithFlags(&evG2a, cudaEventDisableTiming);
    }

    const int edgeBlocks = (NET + 255) / 256;
    const int scanBlocks = (NN + 511) / 512;         // 98

    cudaEventRecord(evFork, 0);
    cudaStreamWaitEvent(s1, evFork, 0);
    cudaMemsetAsync(p_deg, 0, NN * sizeof(int), 0);

    // k1 (side): first half of x + weights
    cvtA_k<<<XBLK + 20, 256, 0, s1>>>(x, W1, W2);
    // k2 (main): second half of x
    cvtB_k<<<XBLK, 256>>>(x);
    cudaEventRecord(evXB, 0);
    // k3 (main)
    count_k<<<edgeBlocks, 256>>>(adj);
    // k4 (side, profiled): gemm1 after both x halves converted
    cudaStreamWaitEvent(s1, evXB, 0);
    gemm_h16_k<<<dim3(HHID / TBN, (NN + TBM - 1) / TBM), 256, GEMM_SMEM, s1>>>(
        p_xh, p_w1t, p_h1h, p_as1, p_ad1, att_src1, att_dst1, NH, NN, HHID, FIN);
    cudaEventRecord(evJoin, s1);

    scan1_k<<<scanBlocks, 512>>>(NN);                                    // k5
    scan23_k<<<scanBlocks, 512>>>(NN);                                   // k6
    scatter_k<<<edgeBlocks, 256>>>(adj);                                 // k7

    // join gemm1 into main; pipeline agg1 with gemm2
    cudaStreamWaitEvent(0, evJoin, 0);
    agg1_k<<<AGG_GRID, 256>>>(b1, 0, NSPLIT);                            // k8 (main)
    cudaEventRecord(evA1a, 0);
    agg1_k<<<AGG_GRID, 256>>>(b1, NSPLIT, NN);                           // k9 (main)

    // side: gemm2 on first node chunk, overlapped with agg1b
    cudaStreamWaitEvent(s1, evA1a, 0);
    gemm_h16_k<<<dim3(OUTC / TBN, NSPLIT / TBM), 256, GEMM_SMEM, s1>>>(  // k10 (side)
        p_heluh, p_w2t, p_h2h, p_as2, p_ad2, att_src2, att_dst2, 1, NSPLIT, OUTC, HHID);
    cudaEventRecord(evG2a, s1);

    // main: gemm2 on second chunk, then agg2 after both
    gemm_h16_k<<<dim3(OUTC / TBN, (NN - NSPLIT + TBM - 1) / TBM), 256, GEMM_SMEM>>>(   // k11
        p_heluh + (size_t)NSPLIT * HHID, p_w2t, p_h2h + (size_t)NSPLIT * OUTC,
        p_as2 + NSPLIT, p_ad2 + NSPLIT, att_src2, att_dst2, 1, NN - NSPLIT, OUTC, HHID);
    cudaStreamWaitEvent(0, evG2a, 0);
    agg2_k<<<AGG_GRID, 256>>>(b2, out);                                  // k12
}